// round 14
// baseline (speedup 1.0000x reference)
#include <cuda_runtime.h>
#include <cuda_bf16.h>
#include <cstdint>

// ---------------------------------------------------------------------------
// GCNCheb via bf16-split GEMMs on the base-target tensor path (mma.sync).
//   out = x(w0-w2) + Y1(w1-w3) + Y2*2w2 + Y3*2w3 + bias,  Yi = L^i x
// Each fp32 GEMM Y = L @ X is 3 bf16 HMMA products (fp32 accumulate):
//   Lhi*Xhi + Lhi*Xlo + Llo*Xhi
// R13: (a) no prep_L — every gemm step reads L in fp32 (same bytes as
//      hi+lo bf16) and splits in registers on the A load path (LDG->cvt->STS);
//      (b) split accumulators (hi-product vs lo-products) to double the
//      independent HMMA dependency chains per warp.
// NOTE: tcgen05/TMEM unavailable (PTX targets compute_103, no 'a').
// ---------------------------------------------------------------------------

namespace {
constexpr int Nn   = 8192;
constexpr int Bb   = 4;
constexpr int FIN  = 32;
constexpr int FOUT = 64;
constexpr int NCOLS = Bb * FIN;          // 128 combined columns
constexpr int BM   = 64;                 // M rows per CTA -> 128 CTAs
constexpr int CK   = 32;                 // K per pipeline chunk
constexpr int NCH  = Nn / CK;            // 256 chunks

// smem tile rows padded to 80 B (40 bf16): conflict-free ldmatrix
constexpr int ROWB   = 80;
constexpr int ST_AH  = 0;
constexpr int ST_AL  = 64 * ROWB;              // 5120
constexpr int ST_BH  = 2 * 64 * ROWB;          // 10240
constexpr int ST_BL  = ST_BH + 128 * ROWB;     // 20480
constexpr int STAGE_B = ST_BL + 128 * ROWB;    // 30720
constexpr int NSTAGE = 4;
constexpr int SMEM_TOTAL = NSTAGE * STAGE_B;   // 122880
}

// ---- device scratch (allocation-free) ----
__device__ __nv_bfloat16 g_B1h[(size_t)NCOLS * Nn], g_B1l[(size_t)NCOLS * Nn];
__device__ __nv_bfloat16 g_B2h[(size_t)NCOLS * Nn], g_B2l[(size_t)NCOLS * Nn];
__device__ __nv_bfloat16 g_B3h[(size_t)NCOLS * Nn], g_B3l[(size_t)NCOLS * Nn];
__device__ __nv_bfloat16 g_B4h[(size_t)NCOLS * Nn], g_B4l[(size_t)NCOLS * Nn];
__device__ float g_Wc[4 * FIN * FOUT];

// ---- PTX helpers (base-target sm_80-class instructions only) ----
__device__ __forceinline__ uint32_t smem_u32(const void* p) {
    uint32_t a;
    asm("{ .reg .u64 t; cvta.to.shared.u64 t, %1; cvt.u32.u64 %0, t; }" : "=r"(a) : "l"(p));
    return a;
}
__device__ __forceinline__ void cp16(uint32_t s, const void* g) {
    asm volatile("cp.async.cg.shared.global [%0], [%1], 16;" :: "r"(s), "l"(g) : "memory");
}
__device__ __forceinline__ void cp_commit() {
    asm volatile("cp.async.commit_group;" ::: "memory");
}
__device__ __forceinline__ void cp_wait2() {
    asm volatile("cp.async.wait_group 2;" ::: "memory");
}
__device__ __forceinline__ void ldsm4(uint32_t* r, uint32_t addr) {
    asm volatile("ldmatrix.sync.aligned.m8n8.x4.shared.b16 {%0,%1,%2,%3}, [%4];"
                 : "=r"(r[0]), "=r"(r[1]), "=r"(r[2]), "=r"(r[3]) : "r"(addr));
}
__device__ __forceinline__ void mma16816(float* c, const uint32_t* a, const uint32_t* b) {
    asm volatile(
        "mma.sync.aligned.m16n8k16.row.col.f32.bf16.bf16.f32 "
        "{%0,%1,%2,%3}, {%4,%5,%6,%7}, {%8,%9}, {%0,%1,%2,%3};"
        : "+f"(c[0]), "+f"(c[1]), "+f"(c[2]), "+f"(c[3])
        : "r"(a[0]), "r"(a[1]), "r"(a[2]), "r"(a[3]), "r"(b[0]), "r"(b[1]));
}
__device__ __forceinline__ uint32_t pack_bf2(__nv_bfloat16 a, __nv_bfloat16 b) {
    return (uint32_t)__bfloat16_as_ushort(a) | ((uint32_t)__bfloat16_as_ushort(b) << 16);
}

// ---------------------------------------------------------------------------
// prep: x [B,N,F] -> B1 split [c=b*32+f][k=n]
// ---------------------------------------------------------------------------
__global__ __launch_bounds__(256, 1) void prep_x(const float* __restrict__ x)
{
    __shared__ float sx[64][FIN];
    const int t  = threadIdx.x;
    const int b  = blockIdx.x >> 7;
    const int n0 = (blockIdx.x & 127) * 64;

    const float4* src = (const float4*)(x + (size_t)b * Nn * FIN + (size_t)n0 * FIN);
    float4* dst = (float4*)&sx[0][0];
    dst[t]       = src[t];
    dst[t + 256] = src[t + 256];
    __syncthreads();

    #pragma unroll
    for (int q = 0; q < 8; ++q) {
        int idx = t + 256 * q;           // 0..2047
        int f = idx >> 6, j = idx & 63;
        float v = sx[j][f];
        __nv_bfloat16 h = __float2bfloat16(v);
        __nv_bfloat16 l = __float2bfloat16(v - __bfloat162float(h));
        size_t off = (size_t)(b * FIN + f) * Nn + n0 + j;
        g_B1h[off] = h;
        g_B1l[off] = l;
    }
}

// ---------------------------------------------------------------------------
// GEMM step: Y[n0:n0+64, 0:128] = L[n0:..] @ X   (3 bf16 HMMA products)
// 16 warps = 4(M) x 4(N); warp tile 16x32.
// A: fp32 LDG -> register split -> STS bf16 (prefetch distance 1 chunk).
// B: 4-stage cp.async pipeline, prefetch distance 3.
// ---------------------------------------------------------------------------
__global__ __launch_bounds__(512, 1) void gemm_tc(const float* __restrict__ Lf, int sel)
{
    const __nv_bfloat16* __restrict__ Bh;
    const __nv_bfloat16* __restrict__ Bl;
    __nv_bfloat16* __restrict__ Oh;
    __nv_bfloat16* __restrict__ Ol;
    if (sel == 0)      { Bh = g_B1h; Bl = g_B1l; Oh = g_B2h; Ol = g_B2l; }
    else if (sel == 1) { Bh = g_B2h; Bl = g_B2l; Oh = g_B3h; Ol = g_B3l; }
    else               { Bh = g_B3h; Bl = g_B3l; Oh = g_B4h; Ol = g_B4l; }

    extern __shared__ __align__(128) char smem[];
    const uint32_t sbase = smem_u32(smem);
    const int t = threadIdx.x, l = t & 31, wid = t >> 5;
    const int wm = wid >> 2, wn = wid & 3;     // 4 x 4 warp grid
    const int n0 = blockIdx.x * BM;

    // ---- A fp32 LDG mapping: 1 float4 (4 k-values) per thread per chunk ----
    const int a_r  = t >> 3;                   // 0..63  (row)
    const int a_ku = t & 7;                    // 0..7   (float4 within 32-k row)
    const float4* gA = (const float4*)(Lf + (size_t)(n0 + a_r) * Nn) + a_ku;
    const uint32_t sAoff = (uint32_t)a_r * ROWB + (uint32_t)a_ku * 8;

    // ---- B cp.async mapping: 2 x 16B per thread per stage ----
    const int b_r = t >> 2;                    // 0..127
    const int b_u = t & 3;
    const __nv_bfloat16* gBh = Bh + (size_t)b_r * Nn + b_u * 8;
    const __nv_bfloat16* gBl = Bl + (size_t)b_r * Nn + b_u * 8;
    const uint32_t sBd = (uint32_t)b_r * ROWB + (uint32_t)b_u * 16;

    // ---- ldmatrix lane offsets ----
    const uint32_t aoff = (uint32_t)(wm * 16 + (l & 15)) * ROWB + (uint32_t)(l >> 4) * 16;
    const uint32_t boff = (uint32_t)(wn * 32 + (l & 7) + ((l >> 4) & 1) * 8) * ROWB
                        + (uint32_t)((l >> 3) & 1) * 16;

    // split accumulators: hi product vs lo products (independent HMMA chains)
    float acc_h[4][4], acc_l[4][4];
    #pragma unroll
    for (int j = 0; j < 4; ++j)
        #pragma unroll
        for (int k = 0; k < 4; ++k) { acc_h[j][k] = 0.0f; acc_l[j][k] = 0.0f; }

    auto sts_A = [&](int stage, float4 v) {
        __nv_bfloat16 h0 = __float2bfloat16(v.x), h1 = __float2bfloat16(v.y);
        __nv_bfloat16 h2 = __float2bfloat16(v.z), h3 = __float2bfloat16(v.w);
        __nv_bfloat16 l0 = __float2bfloat16(v.x - __bfloat162float(h0));
        __nv_bfloat16 l1 = __float2bfloat16(v.y - __bfloat162float(h1));
        __nv_bfloat16 l2 = __float2bfloat16(v.z - __bfloat162float(h2));
        __nv_bfloat16 l3 = __float2bfloat16(v.w - __bfloat162float(h3));
        char* st = smem + (size_t)stage * STAGE_B;
        *(uint2*)(st + ST_AH + sAoff) = make_uint2(pack_bf2(h0, h1), pack_bf2(h2, h3));
        *(uint2*)(st + ST_AL + sAoff) = make_uint2(pack_bf2(l0, l1), pack_bf2(l2, l3));
    };
    auto cpB = [&](int ci) {
        const uint32_t bs = sbase + (uint32_t)(ci % NSTAGE) * STAGE_B;
        const int k0 = ci * CK;
        cp16(bs + ST_BH + sBd, gBh + k0);
        cp16(bs + ST_BL + sBd, gBl + k0);
    };

    // ---- prologue ----
    float4 av;
    av = gA[0 * 8]; sts_A(0, av);
    av = gA[1 * 8]; sts_A(1, av);
    av = gA[2 * 8];                 // chunk 2 held in regs; STS at iter 0
    cpB(0); cp_commit();
    cpB(1); cp_commit();
    cpB(2); cp_commit();

    for (int i = 0; i < NCH; ++i) {
        cp_wait2();            // B stage i landed (<=2 groups outstanding)
        __syncthreads();       // all warps: stage i visible; compute(i-1) done
        if (i + 2 < NCH) sts_A((i + 2) % NSTAGE, av);
        if (i + 3 < NCH) { av = gA[(i + 3) * 8]; cpB(i + 3); }
        cp_commit();

        const uint32_t bs = sbase + (uint32_t)(i % NSTAGE) * STAGE_B;
        #pragma unroll
        for (int kk = 0; kk < 2; ++kk) {
            uint32_t ah[4], al[4], bh[2][4], bl[2][4];
            ldsm4(ah, bs + ST_AH + aoff + kk * 32);
            ldsm4(al, bs + ST_AL + aoff + kk * 32);
            #pragma unroll
            for (int p = 0; p < 2; ++p) {
                ldsm4(bh[p], bs + ST_BH + boff + p * (16 * ROWB) + kk * 32);
                ldsm4(bl[p], bs + ST_BL + boff + p * (16 * ROWB) + kk * 32);
            }
            // hi product -> acc_h ; lo products -> acc_l (independent chains)
            #pragma unroll
            for (int p = 0; p < 2; ++p) {
                mma16816(acc_h[2 * p + 0], ah, &bh[p][0]);
                mma16816(acc_h[2 * p + 1], ah, &bh[p][2]);
                mma16816(acc_l[2 * p + 0], ah, &bl[p][0]);
                mma16816(acc_l[2 * p + 1], ah, &bl[p][2]);
            }
            #pragma unroll
            for (int p = 0; p < 2; ++p) {
                mma16816(acc_l[2 * p + 0], al, &bh[p][0]);
                mma16816(acc_l[2 * p + 1], al, &bh[p][2]);
            }
        }
    }

    // ---- epilogue: fragments -> smem [64][130] fp32 -> split bf16 [c][n] ----
    __syncthreads();
    float* sbuf = (float*)smem;
    #pragma unroll
    for (int nt = 0; nt < 4; ++nt) {
        const int col  = wn * 32 + nt * 8 + (l & 3) * 2;
        const int row0 = wm * 16 + (l >> 2);
        *(float2*)&sbuf[row0 * 130 + col] =
            make_float2(acc_h[nt][0] + acc_l[nt][0], acc_h[nt][1] + acc_l[nt][1]);
        *(float2*)&sbuf[(row0 + 8) * 130 + col] =
            make_float2(acc_h[nt][2] + acc_l[nt][2], acc_h[nt][3] + acc_l[nt][3]);
    }
    __syncthreads();

    #pragma unroll
    for (int job = 0; job < 2; ++job) {
        const int idx = t + 512 * job;      // 0..1023
        const int c = idx >> 3, seg = idx & 7;
        const int nb = seg * 8;
        uint32_t hh[4], ll[4];
        #pragma unroll
        for (int k2 = 0; k2 < 4; ++k2) {
            float v0 = sbuf[(nb + 2 * k2 + 0) * 130 + c];
            float v1 = sbuf[(nb + 2 * k2 + 1) * 130 + c];
            __nv_bfloat16 h0 = __float2bfloat16(v0);
            __nv_bfloat16 h1 = __float2bfloat16(v1);
            __nv_bfloat16 l0 = __float2bfloat16(v0 - __bfloat162float(h0));
            __nv_bfloat16 l1 = __float2bfloat16(v1 - __bfloat162float(h1));
            hh[k2] = pack_bf2(h0, h1);
            ll[k2] = pack_bf2(l0, l1);
        }
        const size_t o = (size_t)c * Nn + n0 + nb;
        *(uint4*)&Oh[o] = make_uint4(hh[0], hh[1], hh[2], hh[3]);
        *(uint4*)&Ol[o] = make_uint4(ll[0], ll[1], ll[2], ll[3]);
    }
}

// ---------------------------------------------------------------------------
// Wc0 = w0 - w2, Wc1 = w1 - w3, Wc2 = 2*w2, Wc3 = 2*w3
// ---------------------------------------------------------------------------
__global__ void combine_w(const float* __restrict__ w)
{
    const int i = blockIdx.x * blockDim.x + threadIdx.x;
    constexpr int S = FIN * FOUT;
    if (i < S) {
        g_Wc[0 * S + i] = w[0 * S + i] - w[2 * S + i];
        g_Wc[1 * S + i] = w[1 * S + i] - w[3 * S + i];
        g_Wc[2 * S + i] = 2.0f * w[2 * S + i];
        g_Wc[3 * S + i] = 2.0f * w[3 * S + i];
    }
}

// ---------------------------------------------------------------------------
// out[r,e] = bias[n,e] + sum_k sum_f S_k[r,f] * Wc[k,f,e]
// ---------------------------------------------------------------------------
__global__ __launch_bounds__(256, 1)
void final_proj(const float* __restrict__ x, const float* __restrict__ bias,
                float* __restrict__ out)
{
    __shared__ __align__(16) float s[4][64][FIN];   // 32 KB

    const int t  = threadIdx.x;
    const int r0 = blockIdx.x * 64;        // r = b*N + n ; 64 | 8192
    const int b  = r0 >> 13;
    const int n0 = r0 & (Nn - 1);

    {
        const float4* src = (const float4*)(x + (size_t)b * Nn * FIN + (size_t)n0 * FIN);
        float4* dst = (float4*)&s[0][0][0];
        dst[t]       = src[t];
        dst[t + 256] = src[t + 256];
    }
    const __nv_bfloat16* Hs[3] = { g_B2h, g_B3h, g_B4h };
    const __nv_bfloat16* Ls[3] = { g_B2l, g_B3l, g_B4l };
    #pragma unroll
    for (int k = 0; k < 3; ++k) {
        #pragma unroll
        for (int q = 0; q < 4; ++q) {
            int idx = t + 256 * q;          // 0..1023
            int f = idx >> 5, jp = idx & 31;
            size_t off = (size_t)(b * FIN + f) * Nn + n0 + 2 * jp;
            __nv_bfloat162 h2 = *(const __nv_bfloat162*)&Hs[k][off];
            __nv_bfloat162 l2 = *(const __nv_bfloat162*)&Ls[k][off];
            s[k + 1][2 * jp + 0][f] = __bfloat162float(h2.x) + __bfloat162float(l2.x);
            s[k + 1][2 * jp + 1][f] = __bfloat162float(h2.y) + __bfloat162float(l2.y);
        }
    }
    __syncthreads();

    const int e  = t & 63;
    const int rq = t >> 6;

    float acc[16];
    #pragma unroll
    for (int i = 0; i < 16; ++i)
        acc[i] = bias[(n0 + rq + 4 * i) * FOUT + e];

    #pragma unroll
    for (int k = 0; k < 4; ++k) {
        #pragma unroll 4
        for (int f = 0; f < FIN; ++f) {
            const float wv = g_Wc[k * (FIN * FOUT) + f * FOUT + e];
            #pragma unroll
            for (int i = 0; i < 16; ++i)
                acc[i] += s[k][rq + 4 * i][f] * wv;
        }
    }
    #pragma unroll
    for (int i = 0; i < 16; ++i)
        out[(size_t)(r0 + rq + 4 * i) * FOUT + e] = acc[i];
}

// ---------------------------------------------------------------------------
extern "C" void kernel_launch(void* const* d_in, const int* in_sizes, int n_in,
                              void* d_out, int out_size)
{
    const float* x  = nullptr;
    const float* Lm = nullptr;
    const float* w  = nullptr;
    const float* bs = nullptr;
    for (int i = 0; i < n_in; ++i) {
        switch (in_sizes[i]) {
            case Bb * Nn * FIN:   x  = (const float*)d_in[i]; break;
            case Nn * Nn:         Lm = (const float*)d_in[i]; break;
            case 4 * FIN * FOUT:  w  = (const float*)d_in[i]; break;
            case Nn * FOUT:       bs = (const float*)d_in[i]; break;
            default: break;
        }
    }
    float* out = (float*)d_out;

    cudaFuncSetAttribute(gemm_tc, cudaFuncAttributeMaxDynamicSharedMemorySize,
                         SMEM_TOTAL);

    combine_w<<<8, 256>>>(w);
    prep_x<<<512, 256>>>(x);
    gemm_tc<<<Nn / BM, 512, SMEM_TOTAL>>>(Lm, 0);   // Y1 = L x
    gemm_tc<<<Nn / BM, 512, SMEM_TOTAL>>>(Lm, 1);   // Y2 = L Y1
    gemm_tc<<<Nn / BM, 512, SMEM_TOTAL>>>(Lm, 2);   // Y3 = L Y2
    final_proj<<<(Bb * Nn) / 64, 256>>>(x, bs, out);
}

// round 17
// speedup vs baseline: 1.0428x; 1.0428x over previous
#include <cuda_runtime.h>
#include <cuda_bf16.h>
#include <cstdint>

// ---------------------------------------------------------------------------
// GCNCheb via bf16-split GEMMs on the base-target tensor path (mma.sync).
//   out = x(w0-w2) + Y1(w1-w3) + Y2*2w2 + Y3*2w3 + bias,  Yi = L^i x
// Each fp32 GEMM Y = L @ X is 3 bf16 HMMA products (fp32 accumulate):
//   Lhi*Xhi + Lhi*Xlo + Llo*Xhi
// R15: A path back to prep_L + pure cp.async (R12 — in-loop cvt/STS was a
//      measured regression: issue-slot pollution); keep ONLY the split
//      accumulators (hi vs lo products) for 2x independent HMMA chains.
// NOTE: tcgen05/TMEM unavailable (PTX targets compute_103, no 'a').
// ---------------------------------------------------------------------------

namespace {
constexpr int Nn   = 8192;
constexpr int Bb   = 4;
constexpr int FIN  = 32;
constexpr int FOUT = 64;
constexpr int NCOLS = Bb * FIN;          // 128 combined columns
constexpr int BM   = 64;                 // M rows per CTA -> 128 CTAs
constexpr int CK   = 32;                 // K per pipeline chunk
constexpr int NCH  = Nn / CK;            // 256 chunks

// smem tile rows padded to 80 B (40 bf16): conflict-free ldmatrix
constexpr int ROWB   = 80;
constexpr int ST_AH  = 0;
constexpr int ST_AL  = 64 * ROWB;              // 5120
constexpr int ST_BH  = 2 * 64 * ROWB;          // 10240
constexpr int ST_BL  = ST_BH + 128 * ROWB;     // 20480
constexpr int STAGE_B = ST_BL + 128 * ROWB;    // 30720
constexpr int NSTAGE = 4;
constexpr int SMEM_TOTAL = NSTAGE * STAGE_B;   // 122880
}

// ---- device scratch (allocation-free) ----
__device__ __nv_bfloat16 g_Lhi[(size_t)Nn * Nn];   // 128 MB
__device__ __nv_bfloat16 g_Llo[(size_t)Nn * Nn];   // 128 MB
__device__ __nv_bfloat16 g_B1h[(size_t)NCOLS * Nn], g_B1l[(size_t)NCOLS * Nn];
__device__ __nv_bfloat16 g_B2h[(size_t)NCOLS * Nn], g_B2l[(size_t)NCOLS * Nn];
__device__ __nv_bfloat16 g_B3h[(size_t)NCOLS * Nn], g_B3l[(size_t)NCOLS * Nn];
__device__ __nv_bfloat16 g_B4h[(size_t)NCOLS * Nn], g_B4l[(size_t)NCOLS * Nn];
__device__ float g_Wc[4 * FIN * FOUT];

// ---- PTX helpers (base-target sm_80-class instructions only) ----
__device__ __forceinline__ uint32_t smem_u32(const void* p) {
    uint32_t a;
    asm("{ .reg .u64 t; cvta.to.shared.u64 t, %1; cvt.u32.u64 %0, t; }" : "=r"(a) : "l"(p));
    return a;
}
__device__ __forceinline__ void cp16(uint32_t s, const void* g) {
    asm volatile("cp.async.cg.shared.global [%0], [%1], 16;" :: "r"(s), "l"(g) : "memory");
}
__device__ __forceinline__ void cp_commit() {
    asm volatile("cp.async.commit_group;" ::: "memory");
}
__device__ __forceinline__ void cp_wait2() {
    asm volatile("cp.async.wait_group 2;" ::: "memory");
}
__device__ __forceinline__ void ldsm4(uint32_t* r, uint32_t addr) {
    asm volatile("ldmatrix.sync.aligned.m8n8.x4.shared.b16 {%0,%1,%2,%3}, [%4];"
                 : "=r"(r[0]), "=r"(r[1]), "=r"(r[2]), "=r"(r[3]) : "r"(addr));
}
__device__ __forceinline__ void mma16816(float* c, const uint32_t* a, const uint32_t* b) {
    asm volatile(
        "mma.sync.aligned.m16n8k16.row.col.f32.bf16.bf16.f32 "
        "{%0,%1,%2,%3}, {%4,%5,%6,%7}, {%8,%9}, {%0,%1,%2,%3};"
        : "+f"(c[0]), "+f"(c[1]), "+f"(c[2]), "+f"(c[3])
        : "r"(a[0]), "r"(a[1]), "r"(a[2]), "r"(a[3]), "r"(b[0]), "r"(b[1]));
}
__device__ __forceinline__ uint32_t pack_bf2(__nv_bfloat16 a, __nv_bfloat16 b) {
    return (uint32_t)__bfloat16_as_ushort(a) | ((uint32_t)__bfloat16_as_ushort(b) << 16);
}

// ---------------------------------------------------------------------------
// prep: split L into bf16 hi/lo (row-major, K-contiguous)
// ---------------------------------------------------------------------------
__global__ void prep_L(const float* __restrict__ L)
{
    const int stride = gridDim.x * blockDim.x;
    for (int i = blockIdx.x * blockDim.x + threadIdx.x; i < Nn * Nn / 4; i += stride) {
        float4 v = ((const float4*)L)[i];
        __nv_bfloat16 h0 = __float2bfloat16(v.x), h1 = __float2bfloat16(v.y);
        __nv_bfloat16 h2 = __float2bfloat16(v.z), h3 = __float2bfloat16(v.w);
        __nv_bfloat16 l0 = __float2bfloat16(v.x - __bfloat162float(h0));
        __nv_bfloat16 l1 = __float2bfloat16(v.y - __bfloat162float(h1));
        __nv_bfloat16 l2 = __float2bfloat16(v.z - __bfloat162float(h2));
        __nv_bfloat16 l3 = __float2bfloat16(v.w - __bfloat162float(h3));
        ((ushort4*)g_Lhi)[i] = make_ushort4(
            __bfloat16_as_ushort(h0), __bfloat16_as_ushort(h1),
            __bfloat16_as_ushort(h2), __bfloat16_as_ushort(h3));
        ((ushort4*)g_Llo)[i] = make_ushort4(
            __bfloat16_as_ushort(l0), __bfloat16_as_ushort(l1),
            __bfloat16_as_ushort(l2), __bfloat16_as_ushort(l3));
    }
}

// ---------------------------------------------------------------------------
// prep: x [B,N,F] -> B1 split [c=b*32+f][k=n]
// ---------------------------------------------------------------------------
__global__ __launch_bounds__(256, 1) void prep_x(const float* __restrict__ x)
{
    __shared__ float sx[64][FIN];
    const int t  = threadIdx.x;
    const int b  = blockIdx.x >> 7;
    const int n0 = (blockIdx.x & 127) * 64;

    const float4* src = (const float4*)(x + (size_t)b * Nn * FIN + (size_t)n0 * FIN);
    float4* dst = (float4*)&sx[0][0];
    dst[t]       = src[t];
    dst[t + 256] = src[t + 256];
    __syncthreads();

    #pragma unroll
    for (int q = 0; q < 8; ++q) {
        int idx = t + 256 * q;           // 0..2047
        int f = idx >> 6, j = idx & 63;
        float v = sx[j][f];
        __nv_bfloat16 h = __float2bfloat16(v);
        __nv_bfloat16 l = __float2bfloat16(v - __bfloat162float(h));
        size_t off = (size_t)(b * FIN + f) * Nn + n0 + j;
        g_B1h[off] = h;
        g_B1l[off] = l;
    }
}

// ---------------------------------------------------------------------------
// GEMM step: Y[n0:n0+64, 0:128] = L[n0:..] @ X   (3 bf16 HMMA products)
// 16 warps = 4(M) x 4(N); warp tile 16x32; 4-stage cp.async pipeline.
// Split accumulators: pass1 -> acc_h ; passes 2,3 -> acc_l.
// ---------------------------------------------------------------------------
__global__ __launch_bounds__(512, 1) void gemm_tc(int sel)
{
    const __nv_bfloat16* __restrict__ Bh;
    const __nv_bfloat16* __restrict__ Bl;
    __nv_bfloat16* __restrict__ Oh;
    __nv_bfloat16* __restrict__ Ol;
    if (sel == 0)      { Bh = g_B1h; Bl = g_B1l; Oh = g_B2h; Ol = g_B2l; }
    else if (sel == 1) { Bh = g_B2h; Bl = g_B2l; Oh = g_B3h; Ol = g_B3l; }
    else               { Bh = g_B3h; Bl = g_B3l; Oh = g_B4h; Ol = g_B4l; }

    extern __shared__ __align__(128) char smem[];
    const uint32_t sbase = smem_u32(smem);
    const int t = threadIdx.x, l = t & 31, wid = t >> 5;
    const int wm = wid >> 2, wn = wid & 3;     // 4 x 4 warp grid
    const int n0 = blockIdx.x * BM;

    // ---- cp.async mapping: exactly 3 x 16B per thread per stage ----
    const int a_hl = t >> 8;
    const int a_r  = (t & 255) >> 2;
    const int a_u  = t & 3;
    const __nv_bfloat16* gA =
        (a_hl ? g_Llo : g_Lhi) + (size_t)(n0 + a_r) * Nn + a_u * 8;
    const uint32_t sAd = (uint32_t)(a_hl ? ST_AL : ST_AH)
                       + (uint32_t)a_r * ROWB + (uint32_t)a_u * 16;
    const int b_r = t >> 2;
    const int b_u = t & 3;
    const __nv_bfloat16* gBh = Bh + (size_t)b_r * Nn + b_u * 8;
    const __nv_bfloat16* gBl = Bl + (size_t)b_r * Nn + b_u * 8;
    const uint32_t sBd = (uint32_t)b_r * ROWB + (uint32_t)b_u * 16;

    // ---- ldmatrix lane offsets ----
    const uint32_t aoff = (uint32_t)(wm * 16 + (l & 15)) * ROWB + (uint32_t)(l >> 4) * 16;
    const uint32_t boff = (uint32_t)(wn * 32 + (l & 7) + ((l >> 4) & 1) * 8) * ROWB
                        + (uint32_t)((l >> 3) & 1) * 16;

    float acc_h[4][4], acc_l[4][4];
    #pragma unroll
    for (int j = 0; j < 4; ++j)
        #pragma unroll
        for (int k = 0; k < 4; ++k) { acc_h[j][k] = 0.0f; acc_l[j][k] = 0.0f; }

    auto issue = [&](int ci) {
        const uint32_t bs = sbase + (uint32_t)(ci % NSTAGE) * STAGE_B;
        const int k0 = ci * CK;
        cp16(bs + sAd, gA + k0);
        cp16(bs + ST_BH + sBd, gBh + k0);
        cp16(bs + ST_BL + sBd, gBl + k0);
    };

    issue(0); cp_commit();
    issue(1); cp_commit();
    issue(2); cp_commit();

    for (int i = 0; i < NCH; ++i) {
        cp_wait2();            // stage i landed (<=2 groups outstanding)
        __syncthreads();       // all warps see stage i; compute(i-1) done
        if (i + 3 < NCH) issue(i + 3);
        cp_commit();

        const uint32_t bs = sbase + (uint32_t)(i % NSTAGE) * STAGE_B;
        #pragma unroll
        for (int kk = 0; kk < 2; ++kk) {
            uint32_t ah[4], al[4], bh[2][4], bl[2][4];
            ldsm4(ah, bs + ST_AH + aoff + kk * 32);
            ldsm4(al, bs + ST_AL + aoff + kk * 32);
            #pragma unroll
            for (int p = 0; p < 2; ++p) {
                ldsm4(bh[p], bs + ST_BH + boff + p * (16 * ROWB) + kk * 32);
                ldsm4(bl[p], bs + ST_BL + boff + p * (16 * ROWB) + kk * 32);
            }
            // hi product -> acc_h ; lo products -> acc_l (independent chains)
            #pragma unroll
            for (int p = 0; p < 2; ++p) {
                mma16816(acc_h[2 * p + 0], ah, &bh[p][0]);
                mma16816(acc_h[2 * p + 1], ah, &bh[p][2]);
                mma16816(acc_l[2 * p + 0], ah, &bl[p][0]);
                mma16816(acc_l[2 * p + 1], ah, &bl[p][2]);
            }
            #pragma unroll
            for (int p = 0; p < 2; ++p) {
                mma16816(acc_l[2 * p + 0], al, &bh[p][0]);
                mma16816(acc_l[2 * p + 1], al, &bh[p][2]);
            }
        }
    }

    // ---- epilogue: fragments -> smem [64][130] fp32 -> split bf16 [c][n] ----
    __syncthreads();
    float* sbuf = (float*)smem;
    #pragma unroll
    for (int nt = 0; nt < 4; ++nt) {
        const int col  = wn * 32 + nt * 8 + (l & 3) * 2;
        const int row0 = wm * 16 + (l >> 2);
        *(float2*)&sbuf[row0 * 130 + col] =
            make_float2(acc_h[nt][0] + acc_l[nt][0], acc_h[nt][1] + acc_l[nt][1]);
        *(float2*)&sbuf[(row0 + 8) * 130 + col] =
            make_float2(acc_h[nt][2] + acc_l[nt][2], acc_h[nt][3] + acc_l[nt][3]);
    }
    __syncthreads();

    #pragma unroll
    for (int job = 0; job < 2; ++job) {
        const int idx = t + 512 * job;      // 0..1023
        const int c = idx >> 3, seg = idx & 7;
        const int nb = seg * 8;
        uint32_t hh[4], ll[4];
        #pragma unroll
        for (int k2 = 0; k2 < 4; ++k2) {
            float v0 = sbuf[(nb + 2 * k2 + 0) * 130 + c];
            float v1 = sbuf[(nb + 2 * k2 + 1) * 130 + c];
            __nv_bfloat16 h0 = __float2bfloat16(v0);
            __nv_bfloat16 h1 = __float2bfloat16(v1);
            __nv_bfloat16 l0 = __float2bfloat16(v0 - __bfloat162float(h0));
            __nv_bfloat16 l1 = __float2bfloat16(v1 - __bfloat162float(h1));
            hh[k2] = pack_bf2(h0, h1);
            ll[k2] = pack_bf2(l0, l1);
        }
        const size_t o = (size_t)c * Nn + n0 + nb;
        *(uint4*)&Oh[o] = make_uint4(hh[0], hh[1], hh[2], hh[3]);
        *(uint4*)&Ol[o] = make_uint4(ll[0], ll[1], ll[2], ll[3]);
    }
}

// ---------------------------------------------------------------------------
// Wc0 = w0 - w2, Wc1 = w1 - w3, Wc2 = 2*w2, Wc3 = 2*w3
// ---------------------------------------------------------------------------
__global__ void combine_w(const float* __restrict__ w)
{
    const int i = blockIdx.x * blockDim.x + threadIdx.x;
    constexpr int S = FIN * FOUT;
    if (i < S) {
        g_Wc[0 * S + i] = w[0 * S + i] - w[2 * S + i];
        g_Wc[1 * S + i] = w[1 * S + i] - w[3 * S + i];
        g_Wc[2 * S + i] = 2.0f * w[2 * S + i];
        g_Wc[3 * S + i] = 2.0f * w[3 * S + i];
    }
}

// ---------------------------------------------------------------------------
// out[r,e] = bias[n,e] + sum_k sum_f S_k[r,f] * Wc[k,f,e]
// ---------------------------------------------------------------------------
__global__ __launch_bounds__(256, 1)
void final_proj(const float* __restrict__ x, const float* __restrict__ bias,
                float* __restrict__ out)
{
    __shared__ __align__(16) float s[4][64][FIN];   // 32 KB

    const int t  = threadIdx.x;
    const int r0 = blockIdx.x * 64;        // r = b*N + n ; 64 | 8192
    const int b  = r0 >> 13;
    const int n0 = r0 & (Nn - 1);

    {
        const float4* src = (const float4*)(x + (size_t)b * Nn * FIN + (size_t)n0 * FIN);
        float4* dst = (float4*)&s[0][0][0];
        dst[t]       = src[t];
        dst[t + 256] = src[t + 256];
    }
    const __nv_bfloat16* Hs[3] = { g_B2h, g_B3h, g_B4h };
    const __nv_bfloat16* Ls[3] = { g_B2l, g_B3l, g_B4l };
    #pragma unroll
    for (int k = 0; k < 3; ++k) {
        #pragma unroll
        for (int q = 0; q < 4; ++q) {
            int idx = t + 256 * q;          // 0..1023
            int f = idx >> 5, jp = idx & 31;
            size_t off = (size_t)(b * FIN + f) * Nn + n0 + 2 * jp;
            __nv_bfloat162 h2 = *(const __nv_bfloat162*)&Hs[k][off];
            __nv_bfloat162 l2 = *(const __nv_bfloat162*)&Ls[k][off];
            s[k + 1][2 * jp + 0][f] = __bfloat162float(h2.x) + __bfloat162float(l2.x);
            s[k + 1][2 * jp + 1][f] = __bfloat162float(h2.y) + __bfloat162float(l2.y);
        }
    }
    __syncthreads();

    const int e  = t & 63;
    const int rq = t >> 6;

    float acc[16];
    #pragma unroll
    for (int i = 0; i < 16; ++i)
        acc[i] = bias[(n0 + rq + 4 * i) * FOUT + e];

    #pragma unroll
    for (int k = 0; k < 4; ++k) {
        #pragma unroll 4
        for (int f = 0; f < FIN; ++f) {
            const float wv = g_Wc[k * (FIN * FOUT) + f * FOUT + e];
            #pragma unroll
            for (int i = 0; i < 16; ++i)
                acc[i] += s[k][rq + 4 * i][f] * wv;
        }
    }
    #pragma unroll
    for (int i = 0; i < 16; ++i)
        out[(size_t)(r0 + rq + 4 * i) * FOUT + e] = acc[i];
}

// ---------------------------------------------------------------------------
extern "C" void kernel_launch(void* const* d_in, const int* in_sizes, int n_in,
                              void* d_out, int out_size)
{
    const float* x  = nullptr;
    const float* Lm = nullptr;
    const float* w  = nullptr;
    const float* bs = nullptr;
    for (int i = 0; i < n_in; ++i) {
        switch (in_sizes[i]) {
            case Bb * Nn * FIN:   x  = (const float*)d_in[i]; break;
            case Nn * Nn:         Lm = (const float*)d_in[i]; break;
            case 4 * FIN * FOUT:  w  = (const float*)d_in[i]; break;
            case Nn * FOUT:       bs = (const float*)d_in[i]; break;
            default: break;
        }
    }
    float* out = (float*)d_out;

    cudaFuncSetAttribute(gemm_tc, cudaFuncAttributeMaxDynamicSharedMemorySize,
                         SMEM_TOTAL);

    combine_w<<<8, 256>>>(w);
    prep_L<<<2048, 256>>>(Lm);
    prep_x<<<512, 256>>>(x);
    gemm_tc<<<Nn / BM, 512, SMEM_TOTAL>>>(0);   // Y1 = L x
    gemm_tc<<<Nn / BM, 512, SMEM_TOTAL>>>(1);   // Y2 = L Y1
    gemm_tc<<<Nn / BM, 512, SMEM_TOTAL>>>(2);   // Y3 = L Y2
    final_proj<<<(Bb * Nn) / 64, 256>>>(x, bs, out);
}